// round 3
// baseline (speedup 1.0000x reference)
#include <cuda_runtime.h>
#include <cstdint>

// Problem constants (D=20, RANK=2 -> o=19 per axis, m=32)
#define O      19
#define DM     20
#define MM     32
#define ROWP   36                    // padded row (floats) -> conflict-free LDS.128
#define CT_STRIDE (MM*ROWP)          // 1152 floats per cos-table slab
#define NT     640                   // 20 warps: (c-pair 0..9) x (d-group 0..1)
#define NITEMS (O*O*2)               // (a,b) x d-half
#define NSITES (DM*DM*DM*DM)         // 160000
#define RCHUNK (DM*DM*MM/4)          // 3200 float4 per R buffer

typedef unsigned long long ull;

// ---- packed f32x2 helpers ----
__device__ __forceinline__ ull f2mul(ull a, ull b) {
    ull r; asm("mul.rn.f32x2 %0, %1, %2;" : "=l"(r) : "l"(a), "l"(b)); return r;
}
__device__ __forceinline__ ull f2fma(ull a, ull b, ull c) {
    ull r; asm("fma.rn.f32x2 %0, %1, %2, %3;" : "=l"(r) : "l"(a), "l"(b), "l"(c)); return r;
}
__device__ __forceinline__ float f2sum(ull v) {
    return __uint_as_float((unsigned)v) + __uint_as_float((unsigned)(v >> 32));
}

// 20.5MB scratch: RM[s, j] = sum_l H[s, l] * M[j, l] / 16
__device__ float g_RM[NSITES * MM];

// ============================ pre-kernel =============================
// RM = (H @ M^T) / 16, site-parallel. lane = j. H row read via broadcast
// LDG.128; output coalesced STG.32.
__global__ void __launch_bounds__(256)
pm4_pre_kernel(const float* __restrict__ H, const float* __restrict__ Mw)
{
    const int lane = threadIdx.x & 31;
    const int gw   = (blockIdx.x * blockDim.x + threadIdx.x) >> 5;
    const int nw   = (gridDim.x * blockDim.x) >> 5;

    // M row for this lane (j = lane), prescaled by 1/16, packed f32x2
    ull Mreg[16];
    {
        const float* mr = Mw + lane * MM;
        #pragma unroll
        for (int k = 0; k < 16; k++) {
            float m0 = mr[2 * k]     * 0.0625f;
            float m1 = mr[2 * k + 1] * 0.0625f;
            Mreg[k] = (ull)__float_as_uint(m0) | ((ull)__float_as_uint(m1) << 32);
        }
    }

    for (int s = gw; s < NSITES; s += nw) {
        const ulonglong2* hrow = (const ulonglong2*)(H + (long)s * MM);
        ull a0 = 0, a1 = 0, a2 = 0, a3 = 0;
        #pragma unroll
        for (int l4 = 0; l4 < 8; l4 += 2) {
            ulonglong2 h0 = hrow[l4];
            ulonglong2 h1 = hrow[l4 + 1];
            a0 = f2fma(Mreg[2 * l4],     h0.x, a0);
            a1 = f2fma(Mreg[2 * l4 + 1], h0.y, a1);
            a2 = f2fma(Mreg[2 * l4 + 2], h1.x, a2);
            a3 = f2fma(Mreg[2 * l4 + 3], h1.y, a3);
        }
        g_RM[(long)s * MM + lane] = (f2sum(a0) + f2sum(a1)) + (f2sum(a2) + f2sum(a3));
    }
}

// ============================ main kernel ============================
// Shared memory layout (floats):
//   Ct  [19][32][36] @ 0      (21888)  Ct[n][i][j] = cos(2*pi*n/(32*i+j+2))
//   Rb  [2][20][20][32] @ 21888 (25600) double-buffered (a,b)-pair sum of RM
//   X   [19][10][32] @ 47488  (6080)   x[c, d-dstart, j] for current item
#define CT_OFF   0
#define R_OFF    21888
#define RBUF     12800
#define X_OFF    47488
#define SMEM_FLOATS 53568
#define SMEM_BYTES (SMEM_FLOATS * 4)

__global__ void __launch_bounds__(NT, 1)
pm4_kernel(const float* __restrict__ P,   // [32,32]
           float* __restrict__ out)       // [19^4, 32]
{
    extern __shared__ float s[];
    float* Ct = s + CT_OFF;
    float* X  = s + X_OFF;

    const int tid  = threadIdx.x;
    const int lane = tid & 31;
    const int w    = tid >> 5;
    const int cp   = w >> 1;          // 0..9
    const int dg   = w & 1;           // 0..1
    const int c0   = 2 * cp;
    const int nc   = (cp == 9) ? 1 : 2;
    const int g    = gridDim.x;

    const float TWO_PI = 6.28318530717958647692f;

    // ---- once per CTA: cos table ----
    for (int e = tid; e < O * MM * MM; e += NT) {
        int n = e >> 10;
        int r = e & 1023;
        int i = r >> 5;
        int j = r & 31;
        float per = (float)(i * MM + j + 2);
        Ct[n * CT_STRIDE + i * ROWP + j] = cosf(TWO_PI * (float)n / per);
    }

    const float* RM = (const float*)g_RM;

    // ---- prologue: load R for first item into buffer 0 ----
    const int item0 = blockIdx.x;
    if (item0 < NITEMS) {
        const int ab = item0 >> 1;
        const int A = ab / O, B = ab % O;
        const int strideB = DM * DM * MM, strideA = DM * strideB;
        const float4* H00 = (const float4*)(RM + (long)A * strideA + (long)B * strideB);
        const float4* H01 = H00 + strideB / 4;
        const float4* H10 = H00 + strideA / 4;
        const float4* H11 = H10 + strideB / 4;
        float4* R4 = (float4*)(s + R_OFF);
        for (int e = tid; e < RCHUNK; e += NT) {
            float4 a = H00[e], b = H01[e], c = H10[e], d = H11[e];
            R4[e] = make_float4(a.x + b.x + c.x + d.x, a.y + b.y + c.y + d.y,
                                a.z + b.z + c.z + d.z, a.w + b.w + c.w + d.w);
        }
    }

    int pb = 0;
    for (int item = item0; item < NITEMS; item += g, pb ^= 1) {
        const int ab = item >> 1;
        const int dh = item & 1;
        const int A = ab / O;
        const int B = ab % O;
        const int dstart = dh ? 10 : 0;
        const int dnum   = dh ? 9 : 10;
        float* Rb = s + R_OFF + pb * RBUF;

        __syncthreads();   // R(item) complete; X free from previous item

        // ---- Phase P (tiny now): x[c,dd,j] = 2x2 window sum of RM pair-sums ----
        {
            const int npairs = O * dnum;
            for (int p = w; p < npairs; p += 20) {
                const int c  = p / dnum;
                const int dd = p - c * dnum;
                const int d  = dstart + dd;
                const float* r0 = &Rb[(c * DM + d) * MM + lane];
                float v = r0[0] + r0[MM] + r0[DM * MM] + r0[DM * MM + MM];
                X[(c * 10 + dd) * 32 + lane] = v;
            }
        }
        __syncthreads();   // X ready for all warps

        // ---- next item's R load, interleaved into phase C below ----
        const float4 *N00 = 0, *N01 = 0, *N10 = 0, *N11 = 0;
        float4* NR4 = 0;
        int e = RCHUNK;    // default: nothing to load
        if (item + g < NITEMS) {
            const int ab2 = (item + g) >> 1;
            const int A2 = ab2 / O, B2 = ab2 % O;
            const int strideB = DM * DM * MM, strideA = DM * strideB;
            N00 = (const float4*)(RM + (long)A2 * strideA + (long)B2 * strideB);
            N01 = N00 + strideB / 4;
            N10 = N00 + strideA / 4;
            N11 = N10 + strideB / 4;
            NR4 = (float4*)(s + R_OFF + (pb ^ 1) * RBUF);
            e = tid;
        }

        // ---- Phase C: contraction. warp = (c-pair, d-group), lane = i ----
        {
            // G = P * Ct[A] * Ct[B] * Ct[c] built directly into registers
            ull G0[16], G1[16];
            {
                const ulonglong2* Pr = (const ulonglong2*)(P + lane * MM);
                const ulonglong2* Ca = (const ulonglong2*)(&Ct[A * CT_STRIDE + lane * ROWP]);
                const ulonglong2* Cb = (const ulonglong2*)(&Ct[B * CT_STRIDE + lane * ROWP]);
                const ulonglong2* Cc0 = (const ulonglong2*)(&Ct[c0 * CT_STRIDE + lane * ROWP]);
                const ulonglong2* Cc1 = (const ulonglong2*)(&Ct[(c0 + 1 < O ? c0 + 1 : c0) * CT_STRIDE + lane * ROWP]);
                #pragma unroll
                for (int l4 = 0; l4 < 8; l4++) {
                    ulonglong2 p2 = Pr[l4];
                    ulonglong2 ca = Ca[l4];
                    ulonglong2 cb = Cb[l4];
                    ull gx = f2mul(f2mul(p2.x, ca.x), cb.x);
                    ull gy = f2mul(f2mul(p2.y, ca.y), cb.y);
                    ulonglong2 c0v = Cc0[l4];
                    G0[2 * l4]     = f2mul(gx, c0v.x);
                    G0[2 * l4 + 1] = f2mul(gy, c0v.y);
                    ulonglong2 c1v = Cc1[l4];
                    G1[2 * l4]     = f2mul(gx, c1v.x);
                    G1[2 * l4 + 1] = f2mul(gy, c1v.y);
                }
            }

            const long outBase = (long)ab * (O * O) * MM;
            for (int dd = dg; dd < dnum; dd += 2) {
                const int d = dstart + dd;
                const float* cdrow = &Ct[d * CT_STRIDE + lane * ROWP];
                const float* xv0p  = &X[(c0 * 10 + dd) * 32];
                const float* xv1p  = &X[((c0 + 1) * 10 + dd) * 32];
                ull A0 = 0, A0b = 0, A1 = 0, A1b = 0;
                #pragma unroll
                for (int l4 = 0; l4 < 8; l4++) {
                    ulonglong2 cd  = *reinterpret_cast<const ulonglong2*>(cdrow + 4 * l4);
                    ulonglong2 xv0 = *reinterpret_cast<const ulonglong2*>(xv0p + 4 * l4);
                    A0  = f2fma(f2mul(cd.x, G0[2 * l4]),     xv0.x, A0);
                    A0b = f2fma(f2mul(cd.y, G0[2 * l4 + 1]), xv0.y, A0b);
                    if (nc == 2) {
                        ulonglong2 xv1 = *reinterpret_cast<const ulonglong2*>(xv1p + 4 * l4);
                        A1  = f2fma(f2mul(cd.x, G1[2 * l4]),     xv1.x, A1);
                        A1b = f2fma(f2mul(cd.y, G1[2 * l4 + 1]), xv1.y, A1b);
                    }
                }
                out[outBase + ((long)c0 * O + d) * MM + lane] = f2sum(A0) + f2sum(A0b);
                if (nc == 2)
                    out[outBase + ((long)(c0 + 1) * O + d) * MM + lane] = f2sum(A1) + f2sum(A1b);

                // interleaved chunks of next item's R load (hides LDG latency)
                #pragma unroll 1
                for (int rep = 0; rep < 3; rep++) {
                    if (e < RCHUNK) {
                        float4 a = N00[e], b = N01[e], c = N10[e], d4 = N11[e];
                        NR4[e] = make_float4(a.x + b.x + c.x + d4.x, a.y + b.y + c.y + d4.y,
                                             a.z + b.z + c.z + d4.z, a.w + b.w + c.w + d4.w);
                        e += NT;
                    }
                }
            }
            // drain remaining R-load chunks
            #pragma unroll 1
            while (e < RCHUNK) {
                float4 a = N00[e], b = N01[e], c = N10[e], d4 = N11[e];
                NR4[e] = make_float4(a.x + b.x + c.x + d4.x, a.y + b.y + c.y + d4.y,
                                     a.z + b.z + c.z + d4.z, a.w + b.w + c.w + d4.w);
                e += NT;
            }
        }
    }
}

extern "C" void kernel_launch(void* const* d_in, const int* in_sizes, int n_in,
                              void* d_out, int out_size)
{
    const float* H  = (const float*)d_in[0];
    const float* Mw = (const float*)d_in[1];
    const float* P  = (const float*)d_in[2];
    float* out = (float*)d_out;

    cudaFuncSetAttribute(pm4_kernel, cudaFuncAttributeMaxDynamicSharedMemorySize, SMEM_BYTES);

    int dev = 0, nsm = 148;
    cudaGetDevice(&dev);
    cudaDeviceGetAttribute(&nsm, cudaDevAttrMultiProcessorCount, dev);
    if (nsm <= 0) nsm = 148;

    pm4_pre_kernel<<<nsm * 2, 256>>>(H, Mw);

    int grid = nsm > NITEMS ? NITEMS : nsm;
    pm4_kernel<<<grid, NT, SMEM_BYTES>>>(P, out);
}